// round 7
// baseline (speedup 1.0000x reference)
#include <cuda_runtime.h>

// Izhikevich RS constants (match reference)
#define P_A 0.02f
#define P_B 0.2f
#define P_C (-65.0f)
#define P_D 8.0f
#define I_TONIC (-3.0f)
// W_rec: diag = 4.0, offdiag = -2.0  =>  I_rec[i] = 6*r[i] - 2*sum(r)
// u' algebra: u + 0.02*(0.2 v - u) = 0.98 u + 0.004 v
// v' algebra: v + (0.04 v^2 + 5 v + 140 - u + I) = 0.04 v^2 + 6 v + (Cc - u + 6 r - 2 rsum)
//             with Cc = 140 + Ip (per-neuron constant)

struct SimState {
    float v[4], u[4], r[4], cnt[4];
};

__device__ __forceinline__ void sim_step(SimState& st, const float* __restrict__ Cc)
{
    const float rsum = (st.r[0] + st.r[1]) + (st.r[2] + st.r[3]);
    #pragma unroll
    for (int i = 0; i < 4; i++) {
        const float K  = fmaf(6.0f, st.r[i], Cc[i] - st.u[i]);   // r-side, overlaps v-side
        const float Kk = fmaf(-2.0f, rsum, K);
        const float vn0 = fmaf(0.04f * st.v[i], st.v[i],
                               fmaf(6.0f, st.v[i], Kk));          // depth 8 from v
        const float un0 = fmaf(0.98f, st.u[i], 0.004f * st.v[i]); // depth 4 from u
        const bool  fired = (vn0 >= 30.0f);
        const float sp = fired ? 1.0f : 0.0f;
        st.v[i]   = fired ? P_C : vn0;
        st.u[i]   = fired ? (un0 + P_D) : un0;
        st.r[i]   = fmaf(0.9f, st.r[i], 0.1f * sp);
        st.cnt[i] += sp;
    }
}

__global__ void __launch_bounds__(512, 1)
spiking_goal_selector_kernel(
    const float* __restrict__ pal_d_rate,   // (3072,)
    const float* __restrict__ neuromod_bias,// (4,)
    const float* __restrict__ W,            // (4, 3072) row-major
    const int*   __restrict__ substeps_p,   // scalar
    float* __restrict__ out, int out_size, int n_e)
{
    __shared__ float part[16];   // one partial per warp, float4-readable

    const int warp = threadIdx.x >> 5;
    const int lane = threadIdx.x & 31;

    // ---- hoisted scalar loads on the sim thread ----
    int    T = 0;
    float4 bias4 = make_float4(0.f, 0.f, 0.f, 0.f);
    if (threadIdx.x == 0) {
        T = *substeps_p;
        bias4 = *reinterpret_cast<const float4*>(neuromod_bias);
    }

    // ---- matvec (measured-best config): 16 warps, 4 per row,
    //      6 fully-unrolled float4 per lane -> whole W in one load wave ----
    const int row = warp >> 2;
    const int p   = warp & 3;
    const int nv4 = n_e >> 2;
    const int q   = nv4 >> 2;          // float4s per warp-slice (192)
    const float4* Wr = reinterpret_cast<const float4*>(W + (size_t)row * n_e) + p * q;
    const float4* xr = reinterpret_cast<const float4*>(pal_d_rate) + p * q;

    float s = 0.0f;
    #pragma unroll 6
    for (int i = lane; i < q; i += 32) {
        float4 w = Wr[i];
        float4 x = xr[i];
        s += w.x * x.x + w.y * x.y + w.z * x.z + w.w * x.w;
    }
    #pragma unroll
    for (int o = 16; o > 0; o >>= 1)
        s += __shfl_down_sync(0xffffffffu, s, o);
    if (lane == 0) part[warp] = s;
    __syncthreads();

    // ---- serial WTA dynamics on thread 0 (4 neurons, T steps) ----
    if (threadIdx.x == 0) {
        const float4* p4 = reinterpret_cast<const float4*>(part);
        float Ip[4];
        float m = 0.0f;
        #pragma unroll
        for (int i = 0; i < 4; i++) {
            const float4 v4 = p4[i];                 // LDS.128, one per row
            Ip[i] = (v4.x + v4.y) + (v4.z + v4.w);
            m += fabsf(Ip[i]);
        }
        m = m * 0.25f + 1e-8f;
        const float scale = (m > 1e-3f) ? (3.0f / m) : 0.0f;
        const float bias[4] = {bias4.x, bias4.y, bias4.z, bias4.w};
        float Cc[4];
        #pragma unroll
        for (int i = 0; i < 4; i++) {
            const float Ipn = fmaf(Ip[i], scale, fmaf(bias[i], 2.0f, I_TONIC));
            Cc[i] = 140.0f + Ipn;                    // per-neuron step constant
        }

        SimState st;
        #pragma unroll
        for (int i = 0; i < 4; i++) {
            st.v[i] = P_C; st.u[i] = P_B * P_C; st.r[i] = 0.0f; st.cnt[i] = 0.0f;
        }

        if (T == 30) {
            #pragma unroll
            for (int t = 0; t < 30; t++) sim_step(st, Cc);   // fully unrolled
        } else {
            for (int t = 0; t < T; t++) sim_step(st, Cc);
        }

        const float invT = 1.0f / (float)T;
        float4 rates;
        rates.x = st.cnt[0] * invT;
        rates.y = st.cnt[1] * invT;
        rates.z = st.cnt[2] * invT;
        rates.w = st.cnt[3] * invT;
        const float rsum2 = (rates.x + rates.y) + (rates.z + rates.w);

        int win = 0; float best = rates.x;
        if (rates.y > best) { best = rates.y; win = 1; }
        if (rates.z > best) { best = rates.z; win = 2; }
        if (rates.w > best) { best = rates.w; win = 3; }

        // Output layout: [rates(4), winner, confidence]
        if (out_size >= 6) {
            *reinterpret_cast<float4*>(out) = rates;
            out[4] = (float)win;
            out[5] = best / (rsum2 + 1e-8f);
        } else {
            float rr[4] = {rates.x, rates.y, rates.z, rates.w};
            for (int i = 0; i < 4 && i < out_size; i++) out[i] = rr[i];
            if (out_size > 4) out[4] = (float)win;
            if (out_size > 5) out[5] = best / (rsum2 + 1e-8f);
        }
    }
}

extern "C" void kernel_launch(void* const* d_in, const int* in_sizes, int n_in,
                              void* d_out, int out_size)
{
    const float* pal_d_rate    = (const float*)d_in[0];   // 3072
    const float* neuromod_bias = (const float*)d_in[1];   // 4
    const float* W_pald_goal   = (const float*)d_in[2];   // 4*3072
    const int*   substeps      = (const int*)  d_in[3];   // 1
    float* out = (float*)d_out;
    const int n_e = in_sizes[0];

    spiking_goal_selector_kernel<<<1, 512>>>(
        pal_d_rate, neuromod_bias, W_pald_goal, substeps, out, out_size, n_e);
}

// round 8
// speedup vs baseline: 1.1272x; 1.1272x over previous
#include <cuda_runtime.h>

// Izhikevich RS constants (match reference)
#define P_A 0.02f
#define P_B 0.2f
#define P_C (-65.0f)
#define P_D 8.0f
#define I_TONIC (-3.0f)
// W_rec: diag = 4.0, offdiag = -2.0  =>  I_rec[i] = 6*r[i] - 2*sum(r)
// u' algebra: u + 0.02*(0.2 v - u) = 0.98 u + 0.004 v
// v' algebra: v + (0.04 v^2 + 5 v + 140 - u + I) = 0.04 v^2 + 6 v + (Cc - u + 6 r - 2 rsum)
//             with Cc = 140 + Ip (per-neuron constant)

struct SimState {
    float v[4], u[4], r[4], cnt[4];
};

__device__ __forceinline__ void sim_step(SimState& st, const float* __restrict__ Cc)
{
    const float rsum = (st.r[0] + st.r[1]) + (st.r[2] + st.r[3]);
    #pragma unroll
    for (int i = 0; i < 4; i++) {
        const float K   = fmaf(6.0f, st.r[i], Cc[i] - st.u[i]);
        const float Kk  = fmaf(-2.0f, rsum, K);
        const float vn0 = fmaf(0.04f * st.v[i], st.v[i],
                               fmaf(6.0f, st.v[i], Kk));
        const float un0 = fmaf(0.98f, st.u[i], 0.004f * st.v[i]);
        const bool  fired = (vn0 >= 30.0f);
        const float sp = fired ? 1.0f : 0.0f;
        st.v[i]   = fired ? P_C : vn0;
        st.u[i]   = fired ? (un0 + P_D) : un0;
        st.r[i]   = fmaf(0.9f, st.r[i], 0.1f * sp);
        st.cnt[i] += sp;
    }
}

__global__ void __launch_bounds__(512, 1)
spiking_goal_selector_kernel(
    const float* __restrict__ pal_d_rate,   // (3072,)
    const float* __restrict__ neuromod_bias,// (4,)
    const float* __restrict__ W,            // (4, 3072) row-major
    const int*   __restrict__ substeps_p,   // scalar
    float* __restrict__ out, int out_size, int n_e)
{
    __shared__ float part[16];   // one partial per warp, float4-readable

    const int warp = threadIdx.x >> 5;
    const int lane = threadIdx.x & 31;

    // ---- hoisted scalar loads (thread 0, consumed after barrier) ----
    int    T = 0;
    float4 bias4 = make_float4(0.f, 0.f, 0.f, 0.f);
    if (threadIdx.x == 0) {
        T = *substeps_p;
        bias4 = *reinterpret_cast<const float4*>(neuromod_bias);
    }

    // ---- matvec (measured-best config): 16 warps, 4 per row,
    //      6 fully-unrolled float4 per lane -> whole W in one load wave ----
    const int row = warp >> 2;
    const int p   = warp & 3;
    const int nv4 = n_e >> 2;
    const int q   = nv4 >> 2;          // float4s per warp-slice (192)
    const float4* Wr = reinterpret_cast<const float4*>(W + (size_t)row * n_e) + p * q;
    const float4* xr = reinterpret_cast<const float4*>(pal_d_rate) + p * q;

    float s = 0.0f;
    #pragma unroll 6
    for (int i = lane; i < q; i += 32) {
        float4 w = Wr[i];
        float4 x = xr[i];
        s += w.x * x.x + w.y * x.y + w.z * x.z + w.w * x.w;
    }
    #pragma unroll
    for (int o = 16; o > 0; o >>= 1)
        s += __shfl_down_sync(0xffffffffu, s, o);
    if (lane == 0) part[warp] = s;
    __syncthreads();

    // ---- serial WTA dynamics on thread 0 (4 neurons, T steps) ----
    if (threadIdx.x == 0) {
        const float4* p4 = reinterpret_cast<const float4*>(part);
        float Ip[4];
        float m = 0.0f;
        #pragma unroll
        for (int i = 0; i < 4; i++) {
            const float4 v4 = p4[i];                 // LDS.128, one per row
            Ip[i] = (v4.x + v4.y) + (v4.z + v4.w);
            m += fabsf(Ip[i]);
        }
        m = m * 0.25f + 1e-8f;
        const float scale = (m > 1e-3f) ? (3.0f / m) : 0.0f;
        const float bias[4] = {bias4.x, bias4.y, bias4.z, bias4.w};
        float Cc[4];
        #pragma unroll
        for (int i = 0; i < 4; i++) {
            const float Ipn = fmaf(Ip[i], scale, fmaf(bias[i], 2.0f, I_TONIC));
            Cc[i] = 140.0f + Ipn;                    // per-neuron step constant
        }

        SimState st;
        #pragma unroll
        for (int i = 0; i < 4; i++) {
            st.v[i] = P_C; st.u[i] = P_B * P_C; st.r[i] = 0.0f; st.cnt[i] = 0.0f;
        }

        if (T == 30) {
            // small warm body (fits L0 I$), 10 loop iterations
            #pragma unroll 3
            for (int t = 0; t < 30; t++) sim_step(st, Cc);
        } else {
            for (int t = 0; t < T; t++) sim_step(st, Cc);
        }

        const float invT = 1.0f / (float)T;
        float4 rates;
        rates.x = st.cnt[0] * invT;
        rates.y = st.cnt[1] * invT;
        rates.z = st.cnt[2] * invT;
        rates.w = st.cnt[3] * invT;
        const float rsum2 = (rates.x + rates.y) + (rates.z + rates.w);

        int win = 0; float best = rates.x;
        if (rates.y > best) { best = rates.y; win = 1; }
        if (rates.z > best) { best = rates.z; win = 2; }
        if (rates.w > best) { best = rates.w; win = 3; }

        // Output layout: [rates(4), winner, confidence]
        if (out_size >= 6) {
            *reinterpret_cast<float4*>(out) = rates;
            out[4] = (float)win;
            out[5] = best / (rsum2 + 1e-8f);
        } else {
            float rr[4] = {rates.x, rates.y, rates.z, rates.w};
            for (int i = 0; i < 4 && i < out_size; i++) out[i] = rr[i];
            if (out_size > 4) out[4] = (float)win;
            if (out_size > 5) out[5] = best / (rsum2 + 1e-8f);
        }
    }
}

extern "C" void kernel_launch(void* const* d_in, const int* in_sizes, int n_in,
                              void* d_out, int out_size)
{
    const float* pal_d_rate    = (const float*)d_in[0];   // 3072
    const float* neuromod_bias = (const float*)d_in[1];   // 4
    const float* W_pald_goal   = (const float*)d_in[2];   // 4*3072
    const int*   substeps      = (const int*)  d_in[3];   // 1
    float* out = (float*)d_out;
    const int n_e = in_sizes[0];

    spiking_goal_selector_kernel<<<1, 512>>>(
        pal_d_rate, neuromod_bias, W_pald_goal, substeps, out, out_size, n_e);
}

// round 9
// speedup vs baseline: 1.1473x; 1.0179x over previous
#include <cuda_runtime.h>

// Izhikevich RS constants (match reference)
#define P_A 0.02f
#define P_B 0.2f
#define P_C (-65.0f)
#define P_D 8.0f
#define I_TONIC (-3.0f)
// W_rec: diag = 4.0, offdiag = -2.0  =>  I_rec[i] = 6*r[i] - 2*sum(r)
// u' algebra: u + 0.02*(0.2 v - u) = 0.98 u + 0.004 v   (verified rel_err 0.0 in R7/R8)
// v' algebra: v' = 0.04 v^2 + 6 v + (Cc - u + 6 r - 2 rsum),  Cc = 140 + Ip

// One sim step, one neuron per lane (groups of 4 lanes replicate the 4-neuron net).
// rsum via width-4 butterfly: bit-identical to serial (r0+r1)+(r2+r3) by commutativity.
__device__ __forceinline__ void sim_step_lane(float& v, float& u, float& r, float& cnt,
                                              float Cc)
{
    const float s1 = r  + __shfl_xor_sync(0xffffffffu, r,  1, 4);
    const float s  = s1 + __shfl_xor_sync(0xffffffffu, s1, 2, 4);
    const float Kk = fmaf(-2.0f, s, fmaf(6.0f, r, Cc - u));
    const float vn = fmaf(0.04f * v, v, fmaf(6.0f, v, Kk));
    const float un = fmaf(0.98f, u, 0.004f * v);
    const bool fired = (vn >= 30.0f);
    v = fired ? P_C : vn;
    u = fired ? (un + P_D) : un;
    r = fmaf(0.9f, r, fired ? 0.1f : 0.0f);
    cnt += fired ? 1.0f : 0.0f;
}

__global__ void __launch_bounds__(512, 1)
spiking_goal_selector_kernel(
    const float* __restrict__ pal_d_rate,   // (3072,)
    const float* __restrict__ neuromod_bias,// (4,)
    const float* __restrict__ W,            // (4, 3072) row-major
    const int*   __restrict__ substeps_p,   // scalar
    float* __restrict__ out, int out_size, int n_e)
{
    __shared__ float part[16];     // one partial per warp, float4-readable
    __shared__ float rates_sh[4];

    const int warp = threadIdx.x >> 5;
    const int lane = threadIdx.x & 31;

    // ---- matvec (measured-best config): 16 warps, 4 per row,
    //      6 fully-unrolled float4 per lane -> whole W in one load wave ----
    const int row = warp >> 2;
    const int p   = warp & 3;
    const int nv4 = n_e >> 2;
    const int q   = nv4 >> 2;          // float4s per warp-slice (192)
    const float4* Wr = reinterpret_cast<const float4*>(W + (size_t)row * n_e) + p * q;
    const float4* xr = reinterpret_cast<const float4*>(pal_d_rate) + p * q;

    float s = 0.0f;
    #pragma unroll 6
    for (int i = lane; i < q; i += 32) {
        float4 w = Wr[i];
        float4 x = xr[i];
        s += w.x * x.x + w.y * x.y + w.z * x.z + w.w * x.w;
    }
    #pragma unroll
    for (int o = 16; o > 0; o >>= 1)
        s += __shfl_down_sync(0xffffffffu, s, o);
    if (lane == 0) part[warp] = s;
    __syncthreads();

    // ---- WTA dynamics on warp 0: one neuron per lane (lane & 3) ----
    if (warp == 0) {
        const int nl = lane & 3;
        const int T = *substeps_p;                      // broadcast LDG

        // Per-lane prologue, serial order (bit-exact vs serial version)
        const float4* p4 = reinterpret_cast<const float4*>(part);
        float Ip[4];
        float m = 0.0f;
        #pragma unroll
        for (int j = 0; j < 4; j++) {
            const float4 v4 = p4[j];
            Ip[j] = (v4.x + v4.y) + (v4.z + v4.w);
            m += fabsf(Ip[j]);
        }
        m = m * 0.25f + 1e-8f;
        const float scale = (m > 1e-3f) ? (3.0f / m) : 0.0f;
        const float bias  = neuromod_bias[nl];          // broadcast per 4-lane group
        const float Cc = 140.0f + fmaf(Ip[nl], scale, fmaf(bias, 2.0f, I_TONIC));

        float v = P_C, u = P_B * P_C, r = 0.0f, cnt = 0.0f;

        if (T == 30) {
            #pragma unroll 5
            for (int t = 0; t < 30; t++) sim_step_lane(v, u, r, cnt, Cc);
        } else {
            for (int t = 0; t < T; t++) sim_step_lane(v, u, r, cnt, Cc);
        }

        const float invT = 1.0f / (float)T;
        if (lane < 4) rates_sh[lane] = cnt * invT;
        __syncwarp();

        if (lane == 0) {
            const float4 rt = *reinterpret_cast<const float4*>(rates_sh);
            const float rsum2 = (rt.x + rt.y) + (rt.z + rt.w);
            int win = 0; float best = rt.x;
            if (rt.y > best) { best = rt.y; win = 1; }
            if (rt.z > best) { best = rt.z; win = 2; }
            if (rt.w > best) { best = rt.w; win = 3; }

            // Output layout: [rates(4), winner, confidence]
            if (out_size >= 6) {
                *reinterpret_cast<float4*>(out) = rt;
                out[4] = (float)win;
                out[5] = best / (rsum2 + 1e-8f);
            } else {
                const float rr[4] = {rt.x, rt.y, rt.z, rt.w};
                for (int i = 0; i < 4 && i < out_size; i++) out[i] = rr[i];
                if (out_size > 4) out[4] = (float)win;
                if (out_size > 5) out[5] = best / (rsum2 + 1e-8f);
            }
        }
    }
}

extern "C" void kernel_launch(void* const* d_in, const int* in_sizes, int n_in,
                              void* d_out, int out_size)
{
    const float* pal_d_rate    = (const float*)d_in[0];   // 3072
    const float* neuromod_bias = (const float*)d_in[1];   // 4
    const float* W_pald_goal   = (const float*)d_in[2];   // 4*3072
    const int*   substeps      = (const int*)  d_in[3];   // 1
    float* out = (float*)d_out;
    const int n_e = in_sizes[0];

    spiking_goal_selector_kernel<<<1, 512>>>(
        pal_d_rate, neuromod_bias, W_pald_goal, substeps, out, out_size, n_e);
}